// round 14
// baseline (speedup 1.0000x reference)
#include <cuda_runtime.h>
#include <cuda_fp16.h>
#include <stdint.h>
#include <math.h>

#define NN 100000
#define NE 1600000
#define DD 128
#define NTILE ((NN + 1023) / 1024)

// ---------------- scratch (static device globals; no allocation) ------------
__device__ __half g_hx[(size_t)NN * DD];
__device__ __half g_bufA[(size_t)NN * DD];
__device__ __half g_bufB[(size_t)NN * DD];
__device__ __half g_hW[4 * DD * DD];
__device__ float  g_inv_out[NN];
__device__ float  g_inv_in[NN];
__device__ int    g_cnt_in[NN];
__device__ int    g_cnt_out[NN];
__device__ int    g_rowstart[NN + 1];
__device__ int    g_cursor[NN];
__device__ int    g_tilesum[NTILE];
__device__ int    g_tileoff[NTILE];
__device__ int    g_colsrc[NE];
__device__ float  g_edgesc[NE];
__device__ float  g_sum[DD];

// ---------------- mma/ldmatrix helpers --------------------------------------
__device__ __forceinline__ unsigned smem_addr_u32(const void* p)
{
    return (unsigned)__cvta_generic_to_shared(p);
}

__device__ __forceinline__ void ldsm4(unsigned* r, unsigned a)
{
    asm volatile("ldmatrix.sync.aligned.m8n8.x4.shared.b16 {%0,%1,%2,%3}, [%4];"
                 : "=r"(r[0]), "=r"(r[1]), "=r"(r[2]), "=r"(r[3]) : "r"(a));
}

__device__ __forceinline__ void ldsm4t(unsigned* r, unsigned a)
{
    asm volatile("ldmatrix.sync.aligned.m8n8.x4.trans.shared.b16 {%0,%1,%2,%3}, [%4];"
                 : "=r"(r[0]), "=r"(r[1]), "=r"(r[2]), "=r"(r[3]) : "r"(a));
}

__device__ __forceinline__ void mma16816(float* c, const unsigned* a,
                                         const unsigned* b)
{
    asm volatile("mma.sync.aligned.m16n8k16.row.col.f32.f16.f16.f32 "
                 "{%0,%1,%2,%3}, {%4,%5,%6,%7}, {%8,%9}, {%0,%1,%2,%3};"
                 : "+f"(c[0]), "+f"(c[1]), "+f"(c[2]), "+f"(c[3])
                 : "r"(a[0]), "r"(a[1]), "r"(a[2]), "r"(a[3]),
                   "r"(b[0]), "r"(b[1]));
}

// pack two floats into one fp16x2 word
__device__ __forceinline__ unsigned pack_h2(float x, float y)
{
    __half2 h = __floats2half2_rn(x, y);
    unsigned u = *(unsigned*)&h;
    return u;
}

// ---------------- x -> fp16 + counter zeroing (fused init) -------------------
__global__ void k_tohalf(const float* __restrict__ x)
{
    int i = blockIdx.x * blockDim.x + threadIdx.x;
    if (i < NN * DD / 4) {
        float4 v = ((const float4*)x)[i];
        uint2 u;
        u.x = pack_h2(v.x, v.y);
        u.y = pack_h2(v.z, v.w);
        ((uint2*)g_hx)[i] = u;
    }
    if (i < NN) {
        g_cnt_in[i] = 0;
        g_cnt_out[i] = 0;
    }
    if (i < DD) {
        g_sum[i] = 0.0f;
    }
}

// ---------------- 4 weights -> fp16 in one launch ----------------------------
__global__ void k_w2h4(const float* __restrict__ W1, const float* __restrict__ W2,
                       const float* __restrict__ W3, const float* __restrict__ W4)
{
    int i = blockIdx.x * blockDim.x + threadIdx.x;   // float4 index over 4 weights
    const int PER_W = DD * DD / 4;                   // 4096
    if (i < 4 * PER_W) {
        int which = i / PER_W;
        int local = i - which * PER_W;
        const float* W = W1;
        if (which == 1) {
            W = W2;
        } else if (which == 2) {
            W = W3;
        } else if (which == 3) {
            W = W4;
        }
        float4 v = ((const float4*)W)[local];
        uint2 u;
        u.x = pack_h2(v.x, v.y);
        u.y = pack_h2(v.z, v.w);
        ((uint2*)g_hW)[i] = u;
    }
}

// ---------------- CSR build -------------------------------------------------
__global__ void k_hist(const int* __restrict__ src, const int* __restrict__ dst)
{
    int e = blockIdx.x * blockDim.x + threadIdx.x;
    if (e < NE) {
        atomicAdd(&g_cnt_out[src[e]], 1);
        atomicAdd(&g_cnt_in[dst[e]], 1);
    }
}

__global__ void k_tilesum()
{
    __shared__ int ws[32];
    int tid = threadIdx.x;
    int idx = blockIdx.x * 1024 + tid;
    int v = (idx < NN) ? g_cnt_in[idx] : 0;
    #pragma unroll
    for (int off = 16; off > 0; off >>= 1) {
        v += __shfl_down_sync(0xffffffffu, v, off);
    }
    if ((tid & 31) == 0) {
        ws[tid >> 5] = v;
    }
    __syncthreads();
    if (tid < 32) {
        int s = ws[tid];
        #pragma unroll
        for (int off = 16; off > 0; off >>= 1) {
            s += __shfl_down_sync(0xffffffffu, s, off);
        }
        if (tid == 0) {
            g_tilesum[blockIdx.x] = s;
        }
    }
}

__global__ void k_tilescan()
{
    __shared__ int s[128];
    int t = threadIdx.x;
    int v = (t < NTILE) ? g_tilesum[t] : 0;
    s[t] = v;
    __syncthreads();
    for (int off = 1; off < 128; off <<= 1) {
        int tv = (t >= off) ? s[t - off] : 0;
        __syncthreads();
        s[t] += tv;
        __syncthreads();
    }
    if (t < NTILE) {
        g_tileoff[t] = s[t] - v;
    }
}

__global__ void k_scan2()
{
    __shared__ int ws[32];
    int tid = threadIdx.x;
    int lane = tid & 31;
    int wid = tid >> 5;
    int idx = blockIdx.x * 1024 + tid;
    int cin = (idx < NN) ? g_cnt_in[idx] : 0;
    int x = cin;
    #pragma unroll
    for (int off = 1; off < 32; off <<= 1) {
        int tv = __shfl_up_sync(0xffffffffu, x, off);
        if (lane >= off) {
            x += tv;
        }
    }
    if (lane == 31) {
        ws[wid] = x;
    }
    __syncthreads();
    if (tid < 32) {
        int s = ws[tid];
        #pragma unroll
        for (int off = 1; off < 32; off <<= 1) {
            int tv = __shfl_up_sync(0xffffffffu, s, off);
            if (tid >= off) {
                s += tv;
            }
        }
        ws[tid] = s;
    }
    __syncthreads();
    int excl = x - cin + ((wid > 0) ? ws[wid - 1] : 0) + g_tileoff[blockIdx.x];
    if (idx < NN) {
        g_rowstart[idx] = excl;
        g_cursor[idx]   = excl;
        g_inv_in[idx]   = rsqrtf(fmaxf((float)cin, 1.0f));
        g_inv_out[idx]  = rsqrtf(fmaxf((float)g_cnt_out[idx], 1.0f));
        if (idx == NN - 1) {
            g_rowstart[NN] = NE;
        }
    }
}

__global__ void k_scatter(const int* __restrict__ src, const int* __restrict__ dst)
{
    int e = blockIdx.x * blockDim.x + threadIdx.x;
    if (e < NE) {
        int d = dst[e];
        int p = atomicAdd(&g_cursor[d], 1);
        int s = src[e];
        g_colsrc[p] = s;
        g_edgesc[p] = g_inv_out[s];
    }
}

// ---------------- fused layer: aggregate into smem + HMMA GEMM --------------
// out = fp16(relu(((A_agg) @ W) * inv_in + b)), where A_agg[r][:] =
// sum_{e in row r} h[src[e]][:] * inv_out[src[e]].
// 256 threads = 8 warps, block tile 64 rows x 128 cols.
// Phase 1: warp w aggregates rows w, w+8, ..., w+56 directly into smem As.
// Phase 2: identical mma.m16n8k16 pipeline as the standalone GEMM.
#define BM 64
#define AS_ST (DD + 8)
__global__ void __launch_bounds__(256, 2)
k_layer(const __half* __restrict__ hin, const __half* __restrict__ Wh,
        const float* __restrict__ bias, __half* __restrict__ out)
{
    extern __shared__ __half smem[];
    __half* As = smem;                    // BM x AS_ST
    __half* Ws = smem + BM * AS_ST;       // DD x AS_ST

    int tid = threadIdx.x;
    int warp = tid >> 5;
    int lane = tid & 31;
    int row0 = blockIdx.x * BM;

    // load W (128x128 fp16 row-major) -> Ws, uint4 = 8 halves
    #pragma unroll
    for (int i = 0; i < (DD * DD / 8) / 256; i++) {
        int idx = tid + i * 256;
        int r = idx >> 4;
        int c8 = idx & 15;
        uint4 v = ((const uint4*)Wh)[idx];
        *(uint4*)(Ws + r * AS_ST + c8 * 8) = v;
    }

    // phase 1: aggregate 8 rows per warp into As (lane covers dims lane*4..+3)
    for (int rr = warp; rr < BM; rr += 8) {
        int node = row0 + rr;
        if (node >= NN) {
            node = NN - 1;   // duplicate work for tail block; stores masked later
        }
        int beg = g_rowstart[node];
        int end = g_rowstart[node + 1];

        float a0x = 0.f, a0y = 0.f, a0z = 0.f, a0w = 0.f;
        float a1x = 0.f, a1y = 0.f, a1z = 0.f, a1w = 0.f;

        int e = beg;
        for (; e + 2 <= end; e += 2) {
            int   s0 = g_colsrc[e];
            int   s1 = g_colsrc[e + 1];
            float c0 = g_edgesc[e];
            float c1 = g_edgesc[e + 1];
            const __half2* p0 = (const __half2*)(hin + (size_t)s0 * DD + lane * 4);
            const __half2* p1 = (const __half2*)(hin + (size_t)s1 * DD + lane * 4);
            __half2 h00 = p0[0];
            __half2 h01 = p0[1];
            __half2 h10 = p1[0];
            __half2 h11 = p1[1];
            float2 f00 = __half22float2(h00);
            float2 f01 = __half22float2(h01);
            float2 f10 = __half22float2(h10);
            float2 f11 = __half22float2(h11);
            a0x = fmaf(f00.x, c0, a0x);
            a0y = fmaf(f00.y, c0, a0y);
            a0z = fmaf(f01.x, c0, a0z);
            a0w = fmaf(f01.y, c0, a0w);
            a1x = fmaf(f10.x, c1, a1x);
            a1y = fmaf(f10.y, c1, a1y);
            a1z = fmaf(f11.x, c1, a1z);
            a1w = fmaf(f11.y, c1, a1w);
        }
        if (e < end) {
            int   s0 = g_colsrc[e];
            float c0 = g_edgesc[e];
            const __half2* p0 = (const __half2*)(hin + (size_t)s0 * DD + lane * 4);
            __half2 h00 = p0[0];
            __half2 h01 = p0[1];
            float2 f00 = __half22float2(h00);
            float2 f01 = __half22float2(h01);
            a0x = fmaf(f00.x, c0, a0x);
            a0y = fmaf(f00.y, c0, a0y);
            a0z = fmaf(f01.x, c0, a0z);
            a0w = fmaf(f01.y, c0, a0w);
        }
        a0x += a1x;
        a0y += a1y;
        a0z += a1z;
        a0w += a1w;

        uint2 u;
        u.x = pack_h2(a0x, a0y);
        u.y = pack_h2(a0z, a0w);
        *(uint2*)(As + rr * AS_ST + lane * 4) = u;
    }
    __syncthreads();

    // phase 2: HMMA GEMM (identical to verified standalone kernel)
    int rs = (warp & 3) * 16;
    int cs = (warp >> 2) * 64;

    float acc[8][4];
    #pragma unroll
    for (int j = 0; j < 8; j++) {
        acc[j][0] = 0.f;
        acc[j][1] = 0.f;
        acc[j][2] = 0.f;
        acc[j][3] = 0.f;
    }

    int lr = lane & 15;
    int lc = (lane >> 4) << 3;

    #pragma unroll
    for (int k0 = 0; k0 < DD; k0 += 16) {
        unsigned a[4];
        unsigned aaddr = smem_addr_u32(As + (rs + lr) * AS_ST + k0 + lc);
        ldsm4(a, aaddr);

        #pragma unroll
        for (int g = 0; g < 4; g++) {
            unsigned b[4];
            unsigned baddr = smem_addr_u32(Ws + (k0 + lr) * AS_ST + cs + g * 16 + lc);
            ldsm4t(b, baddr);
            mma16816(acc[g * 2], a, b);
            mma16816(acc[g * 2 + 1], a, b + 2);
        }
    }

    // epilogue: *inv_in + bias, relu, fp16 store
    int rr2 = lane >> 2;
    int qc = (lane & 3) * 2;
    int r0 = row0 + rs + rr2;
    int r1 = r0 + 8;
    float sc0 = (r0 < NN) ? g_inv_in[r0] : 0.f;
    float sc1 = (r1 < NN) ? g_inv_in[r1] : 0.f;

    #pragma unroll
    for (int j = 0; j < 8; j++) {
        int col = cs + j * 8 + qc;
        float bx = bias[col];
        float by = bias[col + 1];
        if (r0 < NN) {
            float ox = fmaxf(fmaf(acc[j][0], sc0, bx), 0.f);
            float oy = fmaxf(fmaf(acc[j][1], sc0, by), 0.f);
            unsigned u = pack_h2(ox, oy);
            *(unsigned*)(out + (size_t)r0 * DD + col) = u;
        }
        if (r1 < NN) {
            float ox = fmaxf(fmaf(acc[j][2], sc1, bx), 0.f);
            float oy = fmaxf(fmaf(acc[j][3], sc1, by), 0.f);
            unsigned u = pack_h2(ox, oy);
            *(unsigned*)(out + (size_t)r1 * DD + col) = u;
        }
    }
}

// ---------------- mean pool (column sums, fp16 input, half2 reads) ----------
__global__ void k_colsum(const __half* __restrict__ h)
{
    int t = threadIdx.x;  // 64 threads, 2 columns each
    int r0 = blockIdx.x * 256;
    int r1 = r0 + 256;
    if (r1 > NN) {
        r1 = NN;
    }
    float accx = 0.f;
    float accy = 0.f;
    const __half2* h2 = (const __half2*)h;
    for (int r = r0; r < r1; r++) {
        float2 v = __half22float2(h2[(size_t)r * (DD / 2) + t]);
        accx += v.x;
        accy += v.y;
    }
    atomicAdd(&g_sum[t * 2], accx);
    atomicAdd(&g_sum[t * 2 + 1], accy);
}

// ---------------- MLP head --------------------------------------------------
__global__ void k_head(const float* __restrict__ Wl1, const float* __restrict__ bl1,
                       const float* __restrict__ Wl2, const float* __restrict__ bl2,
                       const float* __restrict__ Wo,  const float* __restrict__ bo,
                       float* __restrict__ out)
{
    __shared__ float hg[DD];
    __shared__ float t1[DD];
    __shared__ float red[DD];
    int t = threadIdx.x;  // 128
    hg[t] = g_sum[t] * (1.0f / (float)NN);
    __syncthreads();

    float a = 0.f;
    #pragma unroll 8
    for (int k = 0; k < DD; k++) {
        a = fmaf(hg[k], Wl1[k * DD + t], a);
    }
    t1[t] = fmaxf(a + bl1[t], 0.f);
    __syncthreads();

    float c = 0.f;
    #pragma unroll 8
    for (int k = 0; k < DD; k++) {
        c = fmaf(t1[k], Wl2[k * DD + t], c);
    }
    c = fmaxf(c + bl2[t], 0.f);

    red[t] = c * Wo[t];
    __syncthreads();
    for (int off = 64; off > 0; off >>= 1) {
        if (t < off) {
            red[t] += red[t + off];
        }
        __syncthreads();
    }
    if (t == 0) {
        out[0] = red[0] + bo[0];
    }
}

// ---------------- launch ----------------------------------------------------
extern "C" void kernel_launch(void* const* d_in, const int* in_sizes, int n_in,
                              void* d_out, int out_size)
{
    const float* x   = (const float*)d_in[0];
    const int*   src = (const int*)d_in[1];
    const int*   dst = (const int*)d_in[2];
    const float* W1  = (const float*)d_in[3];
    const float* b1  = (const float*)d_in[4];
    const float* W2  = (const float*)d_in[5];
    const float* b2  = (const float*)d_in[6];
    const float* W3  = (const float*)d_in[7];
    const float* b3  = (const float*)d_in[8];
    const float* W4  = (const float*)d_in[9];
    const float* b4  = (const float*)d_in[10];
    const float* Wl1 = (const float*)d_in[11];
    const float* bl1 = (const float*)d_in[12];
    const float* Wl2 = (const float*)d_in[13];
    const float* bl2 = (const float*)d_in[14];
    const float* Wo  = (const float*)d_in[15];
    const float* bo  = (const float*)d_in[16];
    float* out = (float*)d_out;

    __half* hx = 0;
    __half* bufA = 0;
    __half* bufB = 0;
    __half* hW = 0;
    cudaGetSymbolAddress((void**)&hx,   g_hx);
    cudaGetSymbolAddress((void**)&bufA, g_bufA);
    cudaGetSymbolAddress((void**)&bufB, g_bufB);
    cudaGetSymbolAddress((void**)&hW,   g_hW);

    const int SMEM_BYTES = (BM * AS_ST + DD * AS_ST) * (int)sizeof(__half);
    cudaFuncSetAttribute(k_layer, cudaFuncAttributeMaxDynamicSharedMemorySize,
                         SMEM_BYTES);

    const int nblk_edge = (NE + 255) / 256;
    const int nblk_half = (NN * DD / 4 + 255) / 256;
    const int nblk_w4   = (4 * DD * DD / 4 + 255) / 256;
    const int nblk_gemm = (NN + BM - 1) / BM;
    const int nblk_sum  = (NN + 255) / 256;

    // conversions + counter zeroing, then CSR build
    k_tohalf<<<nblk_half, 256>>>(x);
    k_w2h4<<<nblk_w4, 256>>>(W1, W2, W3, W4);
    k_hist<<<nblk_edge, 256>>>(src, dst);
    k_tilesum<<<NTILE, 1024>>>();
    k_tilescan<<<1, 128>>>();
    k_scan2<<<NTILE, 1024>>>();
    k_scatter<<<nblk_edge, 256>>>(src, dst);

    // 4 fused GCN layers
    k_layer<<<nblk_gemm, 256, SMEM_BYTES>>>(hx,   hW,               b1, bufA);
    k_layer<<<nblk_gemm, 256, SMEM_BYTES>>>(bufA, hW + DD * DD,     b2, bufB);
    k_layer<<<nblk_gemm, 256, SMEM_BYTES>>>(bufB, hW + 2 * DD * DD, b3, bufA);
    k_layer<<<nblk_gemm, 256, SMEM_BYTES>>>(bufA, hW + 3 * DD * DD, b4, bufB);

    // mean pool + head
    k_colsum<<<nblk_sum, 64>>>(bufB);
    k_head<<<1, 128>>>(Wl1, bl1, Wl2, bl2, Wo, bo, out);
}

// round 16
// speedup vs baseline: 1.2816x; 1.2816x over previous
#include <cuda_runtime.h>
#include <cuda_fp16.h>
#include <stdint.h>
#include <math.h>

#define NN 100000
#define NE 1600000
#define DD 128
#define NTILE ((NN + 1023) / 1024)

// ---------------- scratch (static device globals; no allocation) ------------
__device__ __half g_hx[(size_t)NN * DD];
__device__ __half g_bufA[(size_t)NN * DD];
__device__ __half g_bufB[(size_t)NN * DD];
__device__ __half g_agg[(size_t)NN * DD];
__device__ __half g_hW[4 * DD * DD];
__device__ float  g_inv_out[NN];
__device__ float  g_inv_in[NN];
__device__ int    g_cnt_in[NN];
__device__ int    g_cnt_out[NN];
__device__ int    g_rowstart[NN + 1];
__device__ int    g_cursor[NN];
__device__ int    g_tilesum[NTILE];
__device__ int    g_tileoff[NTILE];
__device__ int    g_colsrc[NE];
__device__ float  g_edgesc[NE];
__device__ float  g_sum[DD];

// ---------------- mma/ldmatrix helpers --------------------------------------
__device__ __forceinline__ unsigned smem_addr_u32(const void* p)
{
    return (unsigned)__cvta_generic_to_shared(p);
}

__device__ __forceinline__ void ldsm4(unsigned* r, unsigned a)
{
    asm volatile("ldmatrix.sync.aligned.m8n8.x4.shared.b16 {%0,%1,%2,%3}, [%4];"
                 : "=r"(r[0]), "=r"(r[1]), "=r"(r[2]), "=r"(r[3]) : "r"(a));
}

__device__ __forceinline__ void ldsm4t(unsigned* r, unsigned a)
{
    asm volatile("ldmatrix.sync.aligned.m8n8.x4.trans.shared.b16 {%0,%1,%2,%3}, [%4];"
                 : "=r"(r[0]), "=r"(r[1]), "=r"(r[2]), "=r"(r[3]) : "r"(a));
}

__device__ __forceinline__ void mma16816(float* c, const unsigned* a,
                                         const unsigned* b)
{
    asm volatile("mma.sync.aligned.m16n8k16.row.col.f32.f16.f16.f32 "
                 "{%0,%1,%2,%3}, {%4,%5,%6,%7}, {%8,%9}, {%0,%1,%2,%3};"
                 : "+f"(c[0]), "+f"(c[1]), "+f"(c[2]), "+f"(c[3])
                 : "r"(a[0]), "r"(a[1]), "r"(a[2]), "r"(a[3]),
                   "r"(b[0]), "r"(b[1]));
}

// pack two floats into one fp16x2 word
__device__ __forceinline__ unsigned pack_h2(float x, float y)
{
    __half2 h = __floats2half2_rn(x, y);
    unsigned u = *(unsigned*)&h;
    return u;
}

// ---------------- x -> fp16 + counter zeroing (fused init) -------------------
__global__ void k_tohalf(const float* __restrict__ x)
{
    int i = blockIdx.x * blockDim.x + threadIdx.x;
    if (i < NN * DD / 4) {
        float4 v = ((const float4*)x)[i];
        uint2 u;
        u.x = pack_h2(v.x, v.y);
        u.y = pack_h2(v.z, v.w);
        ((uint2*)g_hx)[i] = u;
    }
    if (i < NN) {
        g_cnt_in[i] = 0;
        g_cnt_out[i] = 0;
    }
    if (i < DD) {
        g_sum[i] = 0.0f;
    }
}

// ---------------- 4 weights -> fp16 in one launch ----------------------------
__global__ void k_w2h4(const float* __restrict__ W1, const float* __restrict__ W2,
                       const float* __restrict__ W3, const float* __restrict__ W4)
{
    int i = blockIdx.x * blockDim.x + threadIdx.x;   // float4 index over 4 weights
    const int PER_W = DD * DD / 4;                   // 4096
    if (i < 4 * PER_W) {
        int which = i / PER_W;
        int local = i - which * PER_W;
        const float* W = W1;
        if (which == 1) {
            W = W2;
        } else if (which == 2) {
            W = W3;
        } else if (which == 3) {
            W = W4;
        }
        float4 v = ((const float4*)W)[local];
        uint2 u;
        u.x = pack_h2(v.x, v.y);
        u.y = pack_h2(v.z, v.w);
        ((uint2*)g_hW)[i] = u;
    }
}

// ---------------- CSR build -------------------------------------------------
__global__ void k_hist(const int* __restrict__ src, const int* __restrict__ dst)
{
    int e = blockIdx.x * blockDim.x + threadIdx.x;
    if (e < NE) {
        atomicAdd(&g_cnt_out[src[e]], 1);
        atomicAdd(&g_cnt_in[dst[e]], 1);
    }
}

__global__ void k_tilesum()
{
    __shared__ int ws[32];
    int tid = threadIdx.x;
    int idx = blockIdx.x * 1024 + tid;
    int v = (idx < NN) ? g_cnt_in[idx] : 0;
    #pragma unroll
    for (int off = 16; off > 0; off >>= 1) {
        v += __shfl_down_sync(0xffffffffu, v, off);
    }
    if ((tid & 31) == 0) {
        ws[tid >> 5] = v;
    }
    __syncthreads();
    if (tid < 32) {
        int s = ws[tid];
        #pragma unroll
        for (int off = 16; off > 0; off >>= 1) {
            s += __shfl_down_sync(0xffffffffu, s, off);
        }
        if (tid == 0) {
            g_tilesum[blockIdx.x] = s;
        }
    }
}

__global__ void k_tilescan()
{
    __shared__ int s[128];
    int t = threadIdx.x;
    int v = (t < NTILE) ? g_tilesum[t] : 0;
    s[t] = v;
    __syncthreads();
    for (int off = 1; off < 128; off <<= 1) {
        int tv = (t >= off) ? s[t - off] : 0;
        __syncthreads();
        s[t] += tv;
        __syncthreads();
    }
    if (t < NTILE) {
        g_tileoff[t] = s[t] - v;
    }
}

__global__ void k_scan2()
{
    __shared__ int ws[32];
    int tid = threadIdx.x;
    int lane = tid & 31;
    int wid = tid >> 5;
    int idx = blockIdx.x * 1024 + tid;
    int cin = (idx < NN) ? g_cnt_in[idx] : 0;
    int x = cin;
    #pragma unroll
    for (int off = 1; off < 32; off <<= 1) {
        int tv = __shfl_up_sync(0xffffffffu, x, off);
        if (lane >= off) {
            x += tv;
        }
    }
    if (lane == 31) {
        ws[wid] = x;
    }
    __syncthreads();
    if (tid < 32) {
        int s = ws[tid];
        #pragma unroll
        for (int off = 1; off < 32; off <<= 1) {
            int tv = __shfl_up_sync(0xffffffffu, s, off);
            if (tid >= off) {
                s += tv;
            }
        }
        ws[tid] = s;
    }
    __syncthreads();
    int excl = x - cin + ((wid > 0) ? ws[wid - 1] : 0) + g_tileoff[blockIdx.x];
    if (idx < NN) {
        g_rowstart[idx] = excl;
        g_cursor[idx]   = excl;
        g_inv_in[idx]   = rsqrtf(fmaxf((float)cin, 1.0f));
        g_inv_out[idx]  = rsqrtf(fmaxf((float)g_cnt_out[idx], 1.0f));
        if (idx == NN - 1) {
            g_rowstart[NN] = NE;
        }
    }
}

__global__ void k_scatter(const int* __restrict__ src, const int* __restrict__ dst)
{
    int e = blockIdx.x * blockDim.x + threadIdx.x;
    if (e < NE) {
        int d = dst[e];
        int p = atomicAdd(&g_cursor[d], 1);
        int s = src[e];
        g_colsrc[p] = s;
        g_edgesc[p] = g_inv_out[s];
    }
}

// ---------------- aggregation: one warp per dst node (fp16 gather) ----------
__global__ void k_aggregate(const __half* __restrict__ h)
{
    int warp = (blockIdx.x * blockDim.x + threadIdx.x) >> 5;
    if (warp >= NN) {
        return;
    }
    int lane = threadIdx.x & 31;

    int beg = g_rowstart[warp];
    int end = g_rowstart[warp + 1];

    float a0x = 0.f, a0y = 0.f, a0z = 0.f, a0w = 0.f;
    float a1x = 0.f, a1y = 0.f, a1z = 0.f, a1w = 0.f;

    int e = beg;
    for (; e + 2 <= end; e += 2) {
        int   s0 = g_colsrc[e];
        int   s1 = g_colsrc[e + 1];
        float c0 = g_edgesc[e];
        float c1 = g_edgesc[e + 1];
        const __half2* p0 = (const __half2*)(h + (size_t)s0 * DD + lane * 4);
        const __half2* p1 = (const __half2*)(h + (size_t)s1 * DD + lane * 4);
        __half2 h00 = p0[0];
        __half2 h01 = p0[1];
        __half2 h10 = p1[0];
        __half2 h11 = p1[1];
        float2 f00 = __half22float2(h00);
        float2 f01 = __half22float2(h01);
        float2 f10 = __half22float2(h10);
        float2 f11 = __half22float2(h11);
        a0x = fmaf(f00.x, c0, a0x);
        a0y = fmaf(f00.y, c0, a0y);
        a0z = fmaf(f01.x, c0, a0z);
        a0w = fmaf(f01.y, c0, a0w);
        a1x = fmaf(f10.x, c1, a1x);
        a1y = fmaf(f10.y, c1, a1y);
        a1z = fmaf(f11.x, c1, a1z);
        a1w = fmaf(f11.y, c1, a1w);
    }
    if (e < end) {
        int   s0 = g_colsrc[e];
        float c0 = g_edgesc[e];
        const __half2* p0 = (const __half2*)(h + (size_t)s0 * DD + lane * 4);
        __half2 h00 = p0[0];
        __half2 h01 = p0[1];
        float2 f00 = __half22float2(h00);
        float2 f01 = __half22float2(h01);
        a0x = fmaf(f00.x, c0, a0x);
        a0y = fmaf(f00.y, c0, a0y);
        a0z = fmaf(f01.x, c0, a0z);
        a0w = fmaf(f01.y, c0, a0w);
    }
    a0x += a1x;
    a0y += a1y;
    a0z += a1z;
    a0w += a1w;

    uint2 u;
    u.x = pack_h2(a0x, a0y);
    u.y = pack_h2(a0z, a0w);
    *(uint2*)(g_agg + (size_t)warp * DD + lane * 4) = u;
}

// ---------------- HMMA GEMM: out = fp16(relu((agg @ W) * inv_in + b)) -------
// 256 threads = 8 warps. Block tile 64x128. Warp (w&3): 16-row slab,
// (w>>2): 64-col half. mma.m16n8k16, A row-major (ldmatrix), B from
// row-major W via ldmatrix.trans.
#define BM 64
#define AS_ST (DD + 8)
__global__ void __launch_bounds__(256, 2)
k_gemm_mma(const __half* __restrict__ Wh, const float* __restrict__ bias,
           __half* __restrict__ out)
{
    extern __shared__ __half smem[];
    __half* As = smem;                    // BM x AS_ST
    __half* Ws = smem + BM * AS_ST;       // DD x AS_ST

    int tid = threadIdx.x;
    int row0 = blockIdx.x * BM;

    // load W (128x128 fp16 row-major) -> Ws, uint4 = 8 halves
    #pragma unroll
    for (int i = 0; i < (DD * DD / 8) / 256; i++) {
        int idx = tid + i * 256;
        int r = idx >> 4;
        int c8 = idx & 15;
        uint4 v = ((const uint4*)Wh)[idx];
        *(uint4*)(Ws + r * AS_ST + c8 * 8) = v;
    }
    // load A tile (BM x 128 fp16) -> As
    #pragma unroll
    for (int i = 0; i < (BM * DD / 8) / 256; i++) {
        int idx = tid + i * 256;
        int r = idx >> 4;
        int c8 = idx & 15;
        int grow = row0 + r;
        if (grow >= NN) {
            grow = NN - 1;
        }
        uint4 v = *(const uint4*)(g_agg + (size_t)grow * DD + c8 * 8);
        *(uint4*)(As + r * AS_ST + c8 * 8) = v;
    }
    __syncthreads();

    int warp = tid >> 5;
    int lane = tid & 31;
    int rs = (warp & 3) * 16;
    int cs = (warp >> 2) * 64;

    float acc[8][4];
    #pragma unroll
    for (int j = 0; j < 8; j++) {
        acc[j][0] = 0.f;
        acc[j][1] = 0.f;
        acc[j][2] = 0.f;
        acc[j][3] = 0.f;
    }

    int lr = lane & 15;
    int lc = (lane >> 4) << 3;

    #pragma unroll
    for (int k0 = 0; k0 < DD; k0 += 16) {
        unsigned a[4];
        unsigned aaddr = smem_addr_u32(As + (rs + lr) * AS_ST + k0 + lc);
        ldsm4(a, aaddr);

        #pragma unroll
        for (int g = 0; g < 4; g++) {
            unsigned b[4];
            unsigned baddr = smem_addr_u32(Ws + (k0 + lr) * AS_ST + cs + g * 16 + lc);
            ldsm4t(b, baddr);
            mma16816(acc[g * 2], a, b);
            mma16816(acc[g * 2 + 1], a, b + 2);
        }
    }

    // epilogue: *inv_in + bias, relu, fp16 store
    int rr = lane >> 2;
    int qc = (lane & 3) * 2;
    int r0 = row0 + rs + rr;
    int r1 = r0 + 8;
    float sc0 = (r0 < NN) ? g_inv_in[r0] : 0.f;
    float sc1 = (r1 < NN) ? g_inv_in[r1] : 0.f;

    #pragma unroll
    for (int j = 0; j < 8; j++) {
        int col = cs + j * 8 + qc;
        float bx = bias[col];
        float by = bias[col + 1];
        if (r0 < NN) {
            float ox = fmaxf(fmaf(acc[j][0], sc0, bx), 0.f);
            float oy = fmaxf(fmaf(acc[j][1], sc0, by), 0.f);
            unsigned u = pack_h2(ox, oy);
            *(unsigned*)(out + (size_t)r0 * DD + col) = u;
        }
        if (r1 < NN) {
            float ox = fmaxf(fmaf(acc[j][2], sc1, bx), 0.f);
            float oy = fmaxf(fmaf(acc[j][3], sc1, by), 0.f);
            unsigned u = pack_h2(ox, oy);
            *(unsigned*)(out + (size_t)r1 * DD + col) = u;
        }
    }
}

// ---------------- mean pool (column sums, fp16 input, half2 reads) ----------
__global__ void k_colsum(const __half* __restrict__ h)
{
    int t = threadIdx.x;  // 64 threads, 2 columns each
    int r0 = blockIdx.x * 256;
    int r1 = r0 + 256;
    if (r1 > NN) {
        r1 = NN;
    }
    float accx = 0.f;
    float accy = 0.f;
    const __half2* h2 = (const __half2*)h;
    for (int r = r0; r < r1; r++) {
        float2 v = __half22float2(h2[(size_t)r * (DD / 2) + t]);
        accx += v.x;
        accy += v.y;
    }
    atomicAdd(&g_sum[t * 2], accx);
    atomicAdd(&g_sum[t * 2 + 1], accy);
}

// ---------------- MLP head --------------------------------------------------
__global__ void k_head(const float* __restrict__ Wl1, const float* __restrict__ bl1,
                       const float* __restrict__ Wl2, const float* __restrict__ bl2,
                       const float* __restrict__ Wo,  const float* __restrict__ bo,
                       float* __restrict__ out)
{
    __shared__ float hg[DD];
    __shared__ float t1[DD];
    __shared__ float red[DD];
    int t = threadIdx.x;  // 128
    hg[t] = g_sum[t] * (1.0f / (float)NN);
    __syncthreads();

    float a = 0.f;
    #pragma unroll 8
    for (int k = 0; k < DD; k++) {
        a = fmaf(hg[k], Wl1[k * DD + t], a);
    }
    t1[t] = fmaxf(a + bl1[t], 0.f);
    __syncthreads();

    float c = 0.f;
    #pragma unroll 8
    for (int k = 0; k < DD; k++) {
        c = fmaf(t1[k], Wl2[k * DD + t], c);
    }
    c = fmaxf(c + bl2[t], 0.f);

    red[t] = c * Wo[t];
    __syncthreads();
    for (int off = 64; off > 0; off >>= 1) {
        if (t < off) {
            red[t] += red[t + off];
        }
        __syncthreads();
    }
    if (t == 0) {
        out[0] = red[0] + bo[0];
    }
}

// ---------------- launch ----------------------------------------------------
extern "C" void kernel_launch(void* const* d_in, const int* in_sizes, int n_in,
                              void* d_out, int out_size)
{
    const float* x   = (const float*)d_in[0];
    const int*   src = (const int*)d_in[1];
    const int*   dst = (const int*)d_in[2];
    const float* W1  = (const float*)d_in[3];
    const float* b1  = (const float*)d_in[4];
    const float* W2  = (const float*)d_in[5];
    const float* b2  = (const float*)d_in[6];
    const float* W3  = (const float*)d_in[7];
    const float* b3  = (const float*)d_in[8];
    const float* W4  = (const float*)d_in[9];
    const float* b4  = (const float*)d_in[10];
    const float* Wl1 = (const float*)d_in[11];
    const float* bl1 = (const float*)d_in[12];
    const float* Wl2 = (const float*)d_in[13];
    const float* bl2 = (const float*)d_in[14];
    const float* Wo  = (const float*)d_in[15];
    const float* bo  = (const float*)d_in[16];
    float* out = (float*)d_out;

    __half* hx = 0;
    __half* bufA = 0;
    __half* bufB = 0;
    __half* hW = 0;
    cudaGetSymbolAddress((void**)&hx,   g_hx);
    cudaGetSymbolAddress((void**)&bufA, g_bufA);
    cudaGetSymbolAddress((void**)&bufB, g_bufB);
    cudaGetSymbolAddress((void**)&hW,   g_hW);

    const int SMEM_BYTES = (BM * AS_ST + DD * AS_ST) * (int)sizeof(__half);
    cudaFuncSetAttribute(k_gemm_mma, cudaFuncAttributeMaxDynamicSharedMemorySize,
                         SMEM_BYTES);

    const int nblk_edge = (NE + 255) / 256;
    const int nblk_half = (NN * DD / 4 + 255) / 256;
    const int nblk_w4   = (4 * DD * DD / 4 + 255) / 256;
    const int nblk_agg  = (NN + 7) / 8;
    const int nblk_gemm = (NN + BM - 1) / BM;
    const int nblk_sum  = (NN + 255) / 256;

    // conversions + counter zeroing, then CSR build
    k_tohalf<<<nblk_half, 256>>>(x);
    k_w2h4<<<nblk_w4, 256>>>(W1, W2, W3, W4);
    k_hist<<<nblk_edge, 256>>>(src, dst);
    k_tilesum<<<NTILE, 1024>>>();
    k_tilescan<<<1, 128>>>();
    k_scan2<<<NTILE, 1024>>>();
    k_scatter<<<nblk_edge, 256>>>(src, dst);

    // 4 GCN layers (split aggregate + GEMM, verified fast path)
    k_aggregate<<<nblk_agg, 256>>>(hx);
    k_gemm_mma<<<nblk_gemm, 256, SMEM_BYTES>>>(hW, b1, bufA);

    k_aggregate<<<nblk_agg, 256>>>(bufA);
    k_gemm_mma<<<nblk_gemm, 256, SMEM_BYTES>>>(hW + DD * DD, b2, bufB);

    k_aggregate<<<nblk_agg, 256>>>(bufB);
    k_gemm_mma<<<nblk_gemm, 256, SMEM_BYTES>>>(hW + 2 * DD * DD, b3, bufA);

    k_aggregate<<<nblk_agg, 256>>>(bufA);
    k_gemm_mma<<<nblk_gemm, 256, SMEM_BYTES>>>(hW + 3 * DD * DD, b4, bufB);

    // mean pool + head
    k_colsum<<<nblk_sum, 64>>>(bufB);
    k_head<<<1, 128>>>(Wl1, bl1, Wl2, bl2, Wo, bo, out);
}